// round 9
// baseline (speedup 1.0000x reference)
#include <cuda_runtime.h>
#include <math.h>

#define BB 64
#define TT 2048
#define FF 64
#define KK 512
#define DD 512
#define LN_EPS 1e-5f
#define G_MIN 0.05f
#define G_MAX 0.95f
#define NSL 16         // split-K slices
#define GRID 129
#define NT 512

// Scratch (__device__ globals; no allocation allowed)
__device__ __align__(16) float gMpart[NSL * DD * FF];   // split-K partials (2MB)
__device__ __align__(16) float gM[DD * FF];             // M = W_w @ P_w, row-major
__device__ __align__(16) float gCp[DD];                 // c' = (W_b+b) - mean
__device__ __align__(16) float gHpart[BB * DD];         // half-1 partial hacc
__device__ unsigned int gBarCnt[3];                     // monotonic ticket barriers

// Grid-wide barrier: all GRID blocks resident (512thr x ~128regs => 1 CTA/SM, GRID<=148).
__device__ __forceinline__ void grid_bar(int which) {
    __syncthreads();
    if (threadIdx.x == 0) {
        __threadfence();
        unsigned int t = atomicAdd(&gBarCnt[which], 1u);
        unsigned int target = (t / GRID + 1u) * GRID;
        volatile unsigned int* p = &gBarCnt[which];
        while (*p < target) { }
        __threadfence();
    }
    __syncthreads();
}

__device__ __forceinline__ unsigned long long pack2(float lo, float hi) {
    unsigned long long r;
    asm("mov.b64 %0, {%1, %2};" : "=l"(r) : "f"(lo), "f"(hi));
    return r;
}
__device__ __forceinline__ void unpack2(unsigned long long p, float& lo, float& hi) {
    asm("mov.b64 {%0, %1}, %2;" : "=f"(lo), "=f"(hi) : "l"(p));
}
// Packed dual-fp32 FMA (Blackwell f32x2 pipe)
__device__ __forceinline__ void fma2(unsigned long long& d, unsigned long long a, unsigned long long b) {
    asm("fma.rn.f32x2 %0, %1, %2, %0;" : "+l"(d) : "l"(a), "l"(b));
}

__global__ void __launch_bounds__(NT, 1)
mega(const float* __restrict__ x,
     const float* __restrict__ th1, const float* __restrict__ ph1,
     const float* __restrict__ th2, const float* __restrict__ ph2,
     const float* __restrict__ w1p, const float* __restrict__ w2p,
     const float* __restrict__ bgp,
     const float* __restrict__ Pw,  const float* __restrict__ Ww,
     const float* __restrict__ Wb,  const float* __restrict__ bvec,
     const float* __restrict__ gamma, const float* __restrict__ beta,
     float* __restrict__ out) {
    __shared__ __align__(16) float sPool[4160];   // P1: sAt 32x66 + sB 32x64 ; blk128: reductions
    __shared__ __align__(16) float sXst[32 * 64]; // staged x chunk (32 timesteps)
    __shared__ float2 sWr[16];
    __shared__ float  sBC[2];

    const int tid = threadIdx.x;
    const int bid = blockIdx.x;
    const int wid = tid >> 5, lane = tid & 31;

    // ---------------- prologue: gate + j-range + first x-chunk staging ----------------
    float g = 0.f, l2omg = 0.f;
    int n = 0, jlo = 0, jhi = 0;
    const int pb = bid & 63;           // batch (phase-3 blocks)
    const float* xb = x + (size_t)pb * TT * FF;
    if (bid < 128) {
        const float z1 = cosf(th1[0]) * cosf(ph1[0]);
        const float z2 = cosf(th2[0]) * cosf(ph2[0]);
        const float zg = w1p[0] * z1 + w2p[0] * z2 + bgp[0];
        g = 1.0f / (1.0f + expf(-zg));
        g = fminf(fmaxf(g, G_MIN), G_MAX);
        const float omg = 1.0f - g;
        l2omg = log2f(omg);
        n = (int)ceilf(-23.03f / logf(omg));
        if (n < 1) n = 1;
        if (n > TT) n = TT;
        const int nh = (n + 1) >> 1;
        jlo = (bid < 64) ? 0 : nh;
        jhi = (bid < 64) ? nh : n;

        // stage first chunk of this block's j-window into sXst (overlaps phase 1)
        const int cnt0 = min(32, jhi - jlo);
        const int q = tid >> 4, f4 = tid & 15;
        if (q < cnt0) {
            const float4* xr = reinterpret_cast<const float4*>(xb + (size_t)(TT - 1 - (jlo + q)) * FF);
            *reinterpret_cast<float4*>(sXst + q * 64 + f4 * 4) = xr[f4];
        }
    }

    // ---------------- Phase 1: 128 GEMM blocks + block 128 (c') ----------------
    if (bid < 128) {
        float* sAt = sPool;               // [k][d] 32x66
        float* sB  = sPool + 32 * 66;     // [k][f] 32x64
        const int ct = bid & 7;           // d tile
        const int ks = bid >> 3;          // k slice
        const int d0 = ct * 64, k0 = ks * 32;

        {   // one float4 of each operand per thread
            const int kq = tid & 7, dy = tid >> 3;     // Ww: 64 rows x 8 float4
            float4 w4 = *reinterpret_cast<const float4*>(Ww + (size_t)(d0 + dy) * KK + k0 + kq * 4);
            sAt[(kq * 4 + 0) * 66 + dy] = w4.x;
            sAt[(kq * 4 + 1) * 66 + dy] = w4.y;
            sAt[(kq * 4 + 2) * 66 + dy] = w4.z;
            sAt[(kq * 4 + 3) * 66 + dy] = w4.w;
            const int fq = tid & 15, ky = tid >> 4;    // Pw: 32 rows x 16 float4
            float4 p4 = *reinterpret_cast<const float4*>(Pw + (size_t)(k0 + ky) * FF + fq * 4);
            *reinterpret_cast<float4*>(sB + ky * 64 + fq * 4) = p4;
        }
        __syncthreads();

        const int tx = tid & 15, ty = tid >> 4;   // 16 f4-cols x 32 d-pairs
        float acc[2][4];
#pragma unroll
        for (int i = 0; i < 2; i++)
#pragma unroll
            for (int j = 0; j < 4; j++) acc[i][j] = 0.f;
#pragma unroll 8
        for (int k = 0; k < 32; k++) {
            float2 a2 = *reinterpret_cast<const float2*>(sAt + k * 66 + ty * 2);
            float4 b4 = *reinterpret_cast<const float4*>(sB + k * 64 + tx * 4);
            acc[0][0] += a2.x * b4.x; acc[0][1] += a2.x * b4.y; acc[0][2] += a2.x * b4.z; acc[0][3] += a2.x * b4.w;
            acc[1][0] += a2.y * b4.x; acc[1][1] += a2.y * b4.y; acc[1][2] += a2.y * b4.z; acc[1][3] += a2.y * b4.w;
        }
        float* outp = gMpart + (size_t)ks * (DD * FF) + (size_t)(d0 + ty * 2) * FF + tx * 4;
#pragma unroll
        for (int i = 0; i < 2; i++) {
            float4 o4 = make_float4(acc[i][0], acc[i][1], acc[i][2], acc[i][3]);
            *reinterpret_cast<float4*>(outp + (size_t)i * FF) = o4;
        }
    } else {
        // block 128: c' = (W_b + b) - mean
        const float cv = Wb[tid] + bvec[tid];
        float s1 = cv;
#pragma unroll
        for (int o = 16; o > 0; o >>= 1) s1 += __shfl_down_sync(0xffffffffu, s1, o);
        if (lane == 0) sPool[wid] = s1;
        __syncthreads();
        if (wid == 0) {
            float t0 = (lane < 16) ? sPool[lane] : 0.f;
#pragma unroll
            for (int o = 8; o > 0; o >>= 1) t0 += __shfl_down_sync(0xffffffffu, t0, o);
            if (lane == 0) sPool[16] = t0;
        }
        __syncthreads();
        const float cbar = sPool[16] * (1.0f / DD);
        gCp[tid] = cv - cbar;
    }

    grid_bar(0);

    // ---------------- Phase 2: blocks 64..127 reduce Mpart -> gM (8 rows each) ----------------
    if (bid >= 64 && bid < 128) {
        const int s = bid - 64;           // 0..63, rows s*8 .. s*8+7
        if (tid < 128) {
            const int dl = tid >> 4, fq = tid & 15;
            const size_t off4 = (size_t)(s * 8 + dl) * 16 + fq;
            const float4* mp4 = reinterpret_cast<const float4*>(gMpart);
            float4 acc = make_float4(0.f, 0.f, 0.f, 0.f);
#pragma unroll
            for (int sl = 0; sl < NSL; sl++) {
                float4 vv = mp4[(size_t)sl * (DD * 16) + off4];
                acc.x += vv.x; acc.y += vv.y; acc.z += vv.z; acc.w += vv.w;
            }
            reinterpret_cast<float4*>(gM)[off4] = acc;
        }
    }

    grid_bar(1);

    // ---------------- Phase 3: 128 blocks (2 per batch), direct y_t path ----------------
    float hacc = 0.f;
    if (bid < 128) {
        // load this thread's M row (d = tid) into registers as f32x2 pairs
        unsigned long long m2[32];
        {
            const ulonglong2* mr = reinterpret_cast<const ulonglong2*>(gM + (size_t)tid * FF);
#pragma unroll
            for (int q = 0; q < 16; q++) {
                ulonglong2 vv = mr[q];
                m2[2 * q + 0] = vv.x;
                m2[2 * q + 1] = vv.y;
            }
        }
        const float cp = gCp[tid];

        for (int jc = jlo; jc < jhi; jc += 32) {
            const int cnt = min(32, jhi - jc);
            if (jc != jlo) {   // first chunk pre-staged before bar0
                __syncthreads();
                const int q = tid >> 4, f4 = tid & 15;
                if (q < cnt) {
                    const float4* xr = reinterpret_cast<const float4*>(xb + (size_t)(TT - 1 - (jc + q)) * FF);
                    *reinterpret_cast<float4*>(sXst + q * 64 + f4 * 4) = xr[f4];
                }
                __syncthreads();
            }
            for (int tq = 0; tq < cnt; tq++) {
                const int j = jc + tq;
                // y = cp + M[tid] . x_t   (packed dual-fp32 FMA)
                unsigned long long acc2a = pack2(cp, 0.f);
                unsigned long long acc2b = pack2(0.f, 0.f);
                const ulonglong2* xs = reinterpret_cast<const ulonglong2*>(sXst + tq * 64);
#pragma unroll
                for (int q = 0; q < 16; q++) {
                    ulonglong2 xv = xs[q];
                    fma2(acc2a, m2[2 * q + 0], xv.x);
                    fma2(acc2b, m2[2 * q + 1], xv.y);
                }
                float lo, hi, lo2, hi2;
                unpack2(acc2a, lo, hi);
                unpack2(acc2b, lo2, hi2);
                const float y = (lo + lo2) + (hi + hi2);

                // block-wide (sum y, sum y^2)
                float s1 = y, s2 = y * y;
#pragma unroll
                for (int o = 16; o > 0; o >>= 1) {
                    s1 += __shfl_down_sync(0xffffffffu, s1, o);
                    s2 += __shfl_down_sync(0xffffffffu, s2, o);
                }
                if (lane == 0) sWr[wid] = make_float2(s1, s2);
                __syncthreads();
                if (wid == 0) {
                    float2 tv = (lane < 16) ? sWr[lane] : make_float2(0.f, 0.f);
#pragma unroll
                    for (int o = 8; o > 0; o >>= 1) {
                        tv.x += __shfl_down_sync(0xffffffffu, tv.x, o);
                        tv.y += __shfl_down_sync(0xffffffffu, tv.y, o);
                    }
                    if (lane == 0) {
                        const float mu = tv.x * (1.0f / DD);
                        const float var = tv.y * (1.0f / DD) - mu * mu;
                        const float w = g * exp2f((float)j * l2omg);
                        sBC[0] = mu;
                        sBC[1] = w * rsqrtf(var + LN_EPS);
                    }
                }
                __syncthreads();
                hacc += sBC[1] * (y - sBC[0]);
            }
        }
        if (bid >= 64) gHpart[(size_t)pb * DD + tid] = hacc;
    }

    grid_bar(2);

    // ---------------- Output: blocks 0..63 combine halves ----------------
    if (bid < 64) {
        const float Wsum = 1.0f - exp2f((float)TT * l2omg);
        const float res = hacc + gHpart[(size_t)bid * DD + tid];
        out[(size_t)bid * DD + tid] = gamma[tid] * res + beta[tid] * Wsum;
    }
}

// ---------------------------------------------------------------------------
// Inputs: x, theta1, phi1, theta2, phi2, w1, w2, b_g, P_w, W_w, W_b, b,
//         ln_gamma, ln_beta, alpha (alpha cancels inside LayerNorm).
// ---------------------------------------------------------------------------
extern "C" void kernel_launch(void* const* d_in, const int* in_sizes, int n_in,
                              void* d_out, int out_size) {
    const float* x     = (const float*)d_in[0];
    const float* th1   = (const float*)d_in[1];
    const float* ph1   = (const float*)d_in[2];
    const float* th2   = (const float*)d_in[3];
    const float* ph2   = (const float*)d_in[4];
    const float* w1p   = (const float*)d_in[5];
    const float* w2p   = (const float*)d_in[6];
    const float* bgp   = (const float*)d_in[7];
    const float* Pw    = (const float*)d_in[8];
    const float* Ww    = (const float*)d_in[9];
    const float* Wb    = (const float*)d_in[10];
    const float* bvec  = (const float*)d_in[11];
    const float* gamma = (const float*)d_in[12];
    const float* beta  = (const float*)d_in[13];

    mega<<<GRID, NT>>>(x, th1, ph1, th2, ph2, w1p, w2p, bgp,
                       Pw, Ww, Wb, bvec, gamma, beta, (float*)d_out);
}

// round 10
// speedup vs baseline: 1.0321x; 1.0321x over previous
#include <cuda_runtime.h>
#include <math.h>

#define BB 64
#define TT 2048
#define FF 64
#define KK 512
#define DD 512
#define LN_EPS 1e-5f
#define G_MIN 0.05f
#define G_MAX 0.95f
#define NSL 16         // split-K slices
#define GRID 129
#define NT 512
#define CH 8           // timesteps per phase-3 chunk

// Scratch (__device__ globals; no allocation allowed)
__device__ __align__(16) float gMpart[NSL * DD * FF];   // split-K partials (2MB)
__device__ __align__(16) float gM[DD * FF];             // M = W_w @ P_w, row-major
__device__ __align__(16) float gCp[DD];                 // c' = (W_b+b) - mean
__device__ unsigned int gBarCnt[2];                     // monotonic ticket barriers

// Grid-wide barrier: all GRID blocks resident (512thr x <=128regs => 1 CTA/SM, GRID<=148).
__device__ __forceinline__ void grid_bar(int which) {
    __syncthreads();
    if (threadIdx.x == 0) {
        __threadfence();
        unsigned int t = atomicAdd(&gBarCnt[which], 1u);
        unsigned int target = (t / GRID + 1u) * GRID;
        volatile unsigned int* p = &gBarCnt[which];
        while (*p < target) { }
        __threadfence();
    }
    __syncthreads();
}

__device__ __forceinline__ unsigned long long pack2(float lo, float hi) {
    unsigned long long r;
    asm("mov.b64 %0, {%1, %2};" : "=l"(r) : "f"(lo), "f"(hi));
    return r;
}
__device__ __forceinline__ void unpack2(unsigned long long p, float& lo, float& hi) {
    asm("mov.b64 {%0, %1}, %2;" : "=f"(lo), "=f"(hi) : "l"(p));
}
// Packed dual-fp32 FMA (Blackwell f32x2 pipe)
__device__ __forceinline__ void fma2(unsigned long long& d, unsigned long long a, unsigned long long b) {
    asm("fma.rn.f32x2 %0, %1, %2, %0;" : "+l"(d) : "l"(a), "l"(b));
}

__global__ void __launch_bounds__(NT, 1)
mega(const float* __restrict__ x,
     const float* __restrict__ th1, const float* __restrict__ ph1,
     const float* __restrict__ th2, const float* __restrict__ ph2,
     const float* __restrict__ w1p, const float* __restrict__ w2p,
     const float* __restrict__ bgp,
     const float* __restrict__ Pw,  const float* __restrict__ Ww,
     const float* __restrict__ Wb,  const float* __restrict__ bvec,
     const float* __restrict__ gamma, const float* __restrict__ beta,
     float* __restrict__ out) {
    __shared__ __align__(16) float sPool[4160];      // P1: sAt 32x66 + sB 32x64
    __shared__ __align__(16) float sXst[CH * 64];    // staged x chunk
    __shared__ __align__(16) float sY[CH * NT];      // y values (16KB)
    __shared__ float2 sW[CH][2];
    __shared__ float  sMu[CH], sCf[CH];

    const int tid = threadIdx.x;
    const int bid = blockIdx.x;
    const int wid = tid >> 5, lane = tid & 31;

    // ---------------- prologue: gate + first x-chunk staging (phase-3 blocks) ----------------
    float g = 0.f, l2omg = 0.f;
    int n = 0;
    const float* xb = x + (size_t)bid * TT * FF;
    if (bid < 64) {
        const float z1 = cosf(th1[0]) * cosf(ph1[0]);
        const float z2 = cosf(th2[0]) * cosf(ph2[0]);
        const float zg = w1p[0] * z1 + w2p[0] * z2 + bgp[0];
        g = 1.0f / (1.0f + expf(-zg));
        g = fminf(fmaxf(g, G_MIN), G_MAX);
        const float omg = 1.0f - g;
        l2omg = log2f(omg);
        n = (int)ceilf(-23.03f / logf(omg));
        if (n < 1) n = 1;
        if (n > TT) n = TT;

        // stage chunk 0 (up to CH timesteps) into sXst — overlaps phase 1
        const int cnt0 = min(CH, n);
        const int q = tid >> 4, f4 = tid & 15;
        if (q < cnt0) {
            const float4* xr = reinterpret_cast<const float4*>(xb + (size_t)(TT - 1 - q) * FF);
            *reinterpret_cast<float4*>(sXst + q * 64 + f4 * 4) = xr[f4];
        }
    }

    // ---------------- Phase 1: 128 GEMM blocks + block 128 (c') ----------------
    if (bid < 128) {
        float* sAt = sPool;               // [k][d] 32x66
        float* sB  = sPool + 32 * 66;     // [k][f] 32x64
        const int ct = bid & 7;           // d tile
        const int ks = bid >> 3;          // k slice
        const int d0 = ct * 64, k0 = ks * 32;

        {
            const int kq = tid & 7, dy = tid >> 3;     // Ww: 64 rows x 8 float4
            float4 w4 = *reinterpret_cast<const float4*>(Ww + (size_t)(d0 + dy) * KK + k0 + kq * 4);
            sAt[(kq * 4 + 0) * 66 + dy] = w4.x;
            sAt[(kq * 4 + 1) * 66 + dy] = w4.y;
            sAt[(kq * 4 + 2) * 66 + dy] = w4.z;
            sAt[(kq * 4 + 3) * 66 + dy] = w4.w;
            const int fq = tid & 15, ky = tid >> 4;    // Pw: 32 rows x 16 float4
            float4 p4 = *reinterpret_cast<const float4*>(Pw + (size_t)(k0 + ky) * FF + fq * 4);
            *reinterpret_cast<float4*>(sB + ky * 64 + fq * 4) = p4;
        }
        __syncthreads();

        const int tx = tid & 15, ty = tid >> 4;   // 16 f4-cols x 32 d-pairs
        float acc[2][4];
#pragma unroll
        for (int i = 0; i < 2; i++)
#pragma unroll
            for (int j = 0; j < 4; j++) acc[i][j] = 0.f;
#pragma unroll 8
        for (int k = 0; k < 32; k++) {
            float2 a2 = *reinterpret_cast<const float2*>(sAt + k * 66 + ty * 2);
            float4 b4 = *reinterpret_cast<const float4*>(sB + k * 64 + tx * 4);
            acc[0][0] += a2.x * b4.x; acc[0][1] += a2.x * b4.y; acc[0][2] += a2.x * b4.z; acc[0][3] += a2.x * b4.w;
            acc[1][0] += a2.y * b4.x; acc[1][1] += a2.y * b4.y; acc[1][2] += a2.y * b4.z; acc[1][3] += a2.y * b4.w;
        }
        float* outp = gMpart + (size_t)ks * (DD * FF) + (size_t)(d0 + ty * 2) * FF + tx * 4;
#pragma unroll
        for (int i = 0; i < 2; i++) {
            float4 o4 = make_float4(acc[i][0], acc[i][1], acc[i][2], acc[i][3]);
            *reinterpret_cast<float4*>(outp + (size_t)i * FF) = o4;
        }
    } else {
        // block 128: c' = (W_b + b) - mean
        const float cv = Wb[tid] + bvec[tid];
        float s1 = cv;
#pragma unroll
        for (int o = 16; o > 0; o >>= 1) s1 += __shfl_down_sync(0xffffffffu, s1, o);
        if (lane == 0) sPool[wid] = s1;
        __syncthreads();
        if (wid == 0) {
            float t0 = (lane < 16) ? sPool[lane] : 0.f;
#pragma unroll
            for (int o = 8; o > 0; o >>= 1) t0 += __shfl_down_sync(0xffffffffu, t0, o);
            if (lane == 0) sPool[16] = t0;
        }
        __syncthreads();
        const float cbar = sPool[16] * (1.0f / DD);
        gCp[tid] = cv - cbar;
    }

    grid_bar(0);

    // ---------------- Phase 2: blocks 64..127 reduce Mpart -> gM (8 rows each) ----------------
    if (bid >= 64 && bid < 128) {
        const int s = bid - 64;
        if (tid < 128) {
            const int dl = tid >> 4, fq = tid & 15;
            const size_t off4 = (size_t)(s * 8 + dl) * 16 + fq;
            const float4* mp4 = reinterpret_cast<const float4*>(gMpart);
            float4 acc = make_float4(0.f, 0.f, 0.f, 0.f);
#pragma unroll
            for (int sl = 0; sl < NSL; sl++) {
                float4 vv = mp4[(size_t)sl * (DD * 16) + off4];
                acc.x += vv.x; acc.y += vv.y; acc.z += vv.z; acc.w += vv.w;
            }
            reinterpret_cast<float4*>(gM)[off4] = acc;
        }
    }

    grid_bar(1);

    // ---------------- Phase 3: blocks 0..63, one per batch ----------------
    if (bid >= 64) return;
    {
        // this thread's M row (d = tid) as f32x2 pairs
        unsigned long long m2[32];
        {
            const ulonglong2* mr = reinterpret_cast<const ulonglong2*>(gM + (size_t)tid * FF);
#pragma unroll
            for (int q = 0; q < 16; q++) {
                ulonglong2 vv = mr[q];
                m2[2 * q + 0] = vv.x;
                m2[2 * q + 1] = vv.y;
            }
        }
        const float cp = gCp[tid];
        float hacc = 0.f;

        for (int jc = 0; jc < n; jc += CH) {
            const int cnt = min(CH, n - jc);
            if (jc != 0) {
                __syncthreads();   // protect sXst/sY overwrite
                const int q = tid >> 4, f4 = tid & 15;
                if (q < cnt) {
                    const float4* xr = reinterpret_cast<const float4*>(xb + (size_t)(TT - 1 - (jc + q)) * FF);
                    *reinterpret_cast<float4*>(sXst + q * 64 + f4 * 4) = xr[f4];
                }
                __syncthreads();
            }

            // compute y for all cnt timesteps (no syncs, pure FFMA2 stream)
#pragma unroll
            for (int tq = 0; tq < CH; tq++) {
                if (tq < cnt) {
                    unsigned long long acc2a = pack2(cp, 0.f);
                    unsigned long long acc2b = pack2(0.f, 0.f);
                    const ulonglong2* xs = reinterpret_cast<const ulonglong2*>(sXst + tq * 64);
#pragma unroll
                    for (int q = 0; q < 16; q++) {
                        ulonglong2 xv = xs[q];
                        fma2(acc2a, m2[2 * q + 0], xv.x);
                        fma2(acc2b, m2[2 * q + 1], xv.y);
                    }
                    float lo, hi, lo2, hi2;
                    unpack2(acc2a, lo, hi);
                    unpack2(acc2b, lo2, hi2);
                    sY[tq * NT + tid] = (lo + lo2) + (hi + hi2);
                } else {
                    sY[tq * NT + tid] = 0.f;
                }
            }
            __syncthreads();

            // fused reduction: 2 warps per timestep, (sum y, sum y^2)
            {
                const int t = wid >> 1, seg = wid & 1;
                const float* yr = sY + t * NT + seg * 256;
                float s1 = 0.f, s2 = 0.f;
#pragma unroll
                for (int i = 0; i < 8; i++) {
                    float vv = yr[lane + 32 * i];
                    s1 += vv;
                    s2 += vv * vv;
                }
#pragma unroll
                for (int o = 16; o > 0; o >>= 1) {
                    s1 += __shfl_down_sync(0xffffffffu, s1, o);
                    s2 += __shfl_down_sync(0xffffffffu, s2, o);
                }
                if (lane == 0) sW[t][seg] = make_float2(s1, s2);
            }
            __syncthreads();
            if (wid == 0 && lane < CH) {
                float2 a = sW[lane][0], b = sW[lane][1];
                const float ysum = a.x + b.x;
                const float y2sum = a.y + b.y;
                const float mu = ysum * (1.0f / DD);
                const float var = y2sum * (1.0f / DD) - mu * mu;
                float coef = 0.f;
                if (lane < cnt)
                    coef = g * exp2f((float)(jc + lane) * l2omg) * rsqrtf(var + LN_EPS);
                sMu[lane] = mu;
                sCf[lane] = coef;
            }
            __syncthreads();

#pragma unroll
            for (int t = 0; t < CH; t++) {
                if (t < cnt)
                    hacc += sCf[t] * (sY[t * NT + tid] - sMu[t]);
            }
        }

        const float Wsum = 1.0f - exp2f((float)TT * l2omg);
        out[(size_t)bid * DD + tid] = gamma[tid] * hacc + beta[tid] * Wsum;
    }
}

// ---------------------------------------------------------------------------
// Inputs: x, theta1, phi1, theta2, phi2, w1, w2, b_g, P_w, W_w, W_b, b,
//         ln_gamma, ln_beta, alpha (alpha cancels inside LayerNorm).
// ---------------------------------------------------------------------------
extern "C" void kernel_launch(void* const* d_in, const int* in_sizes, int n_in,
                              void* d_out, int out_size) {
    const float* x     = (const float*)d_in[0];
    const float* th1   = (const float*)d_in[1];
    const float* ph1   = (const float*)d_in[2];
    const float* th2   = (const float*)d_in[3];
    const float* ph2   = (const float*)d_in[4];
    const float* w1p   = (const float*)d_in[5];
    const float* w2p   = (const float*)d_in[6];
    const float* bgp   = (const float*)d_in[7];
    const float* Pw    = (const float*)d_in[8];
    const float* Ww    = (const float*)d_in[9];
    const float* Wb    = (const float*)d_in[10];
    const float* bvec  = (const float*)d_in[11];
    const float* gamma = (const float*)d_in[12];
    const float* beta  = (const float*)d_in[13];

    mega<<<GRID, NT>>>(x, th1, ph1, th2, ph2, w1p, w2p, bgp,
                       Pw, Ww, Wb, bvec, gamma, beta, (float*)d_out);
}

// round 11
// speedup vs baseline: 1.1421x; 1.1066x over previous
#include <cuda_runtime.h>
#include <math.h>

#define BB 64
#define TT 2048
#define FF 64
#define KK 512
#define DD 512
#define LN_EPS 1e-5f
#define G_MIN 0.05f
#define G_MAX 0.95f
#define NSL 16         // split-K slices
#define GRID 129
#define NT 512
#define CH 16          // timesteps per phase-3 chunk (n~12 -> single chunk)

// Scratch (__device__ globals; no allocation allowed). Zero-initialized at load;
// gMt is re-zeroed at the end of every call (steady-state invariant).
__device__ __align__(16) float gMt[FF * DD];            // M transposed [f][d], red.add target
__device__ __align__(16) float gCp[DD];                 // c' = (W_b+b) - mean
__device__ unsigned int gProdDone;                      // 129 signals per call (monotonic)
__device__ unsigned int gReadDone;                      // 64 signals per call (monotonic)

__device__ __forceinline__ unsigned long long pack2(float lo, float hi) {
    unsigned long long r;
    asm("mov.b64 %0, {%1, %2};" : "=l"(r) : "f"(lo), "f"(hi));
    return r;
}
__device__ __forceinline__ void unpack2(unsigned long long p, float& lo, float& hi) {
    asm("mov.b64 {%0, %1}, %2;" : "=f"(lo), "=f"(hi) : "l"(p));
}
// Packed dual-fp32 FMA (Blackwell f32x2 pipe)
__device__ __forceinline__ void fma2(unsigned long long& d, unsigned long long a, unsigned long long b) {
    asm("fma.rn.f32x2 %0, %1, %2, %0;" : "+l"(d) : "l"(a), "l"(b));
}
__device__ __forceinline__ void redadd(float* p, float v) {
    asm volatile("red.global.add.f32 [%0], %1;" :: "l"(p), "f"(v) : "memory");
}

__global__ void __launch_bounds__(NT, 1)
mega(const float* __restrict__ x,
     const float* __restrict__ th1, const float* __restrict__ ph1,
     const float* __restrict__ th2, const float* __restrict__ ph2,
     const float* __restrict__ w1p, const float* __restrict__ w2p,
     const float* __restrict__ bgp,
     const float* __restrict__ Pw,  const float* __restrict__ Ww,
     const float* __restrict__ Wb,  const float* __restrict__ bvec,
     const float* __restrict__ gamma, const float* __restrict__ beta,
     float* __restrict__ out) {
    __shared__ __align__(16) float sBig[CH * NT];    // 32KB: GEMM tiles (4160 fl) OR sY
    __shared__ __align__(16) float sXst[CH * 64];    // staged x chunk (4KB)
    __shared__ float sMu[CH], sCf[CH];
    __shared__ unsigned int sEpoch;

    const int tid = threadIdx.x;
    const int bid = blockIdx.x;
    const int wid = tid >> 5, lane = tid & 31;

    // ---------------- prologue: gate + chunk-0 x staging (blocks 0..63) ----------------
    float g = 0.f, l2omg = 0.f;
    int n = 0;
    const float* xb = x + (size_t)bid * TT * FF;
    if (bid < 64) {
        const float z1 = cosf(th1[0]) * cosf(ph1[0]);
        const float z2 = cosf(th2[0]) * cosf(ph2[0]);
        const float zg = w1p[0] * z1 + w2p[0] * z2 + bgp[0];
        g = 1.0f / (1.0f + expf(-zg));
        g = fminf(fmaxf(g, G_MIN), G_MAX);
        const float omg = 1.0f - g;
        l2omg = log2f(omg);
        n = (int)ceilf(-23.03f / logf(omg));
        if (n < 1) n = 1;
        if (n > TT) n = TT;

        const int cnt0 = min(CH, n);
        const int q = tid >> 4, f4 = tid & 15;
        if (q < cnt0) {
            const float4* xr = reinterpret_cast<const float4*>(xb + (size_t)(TT - 1 - q) * FF);
            *reinterpret_cast<float4*>(sXst + q * 64 + f4 * 4) = xr[f4];
        }
    }

    // ---------------- Phase 1: 128 GEMM blocks (red.add into gMt) + block 128 (c') ----------------
    if (bid < 128) {
        float* sAt = sBig;                // [k][d] 32x66
        float* sB  = sBig + 32 * 66;      // [k][f] 32x64
        const int ct = bid & 7;           // d tile
        const int ks = bid >> 3;          // k slice (16)
        const int d0 = ct * 64, k0 = ks * 32;

        {
            const int kq = tid & 7, dy = tid >> 3;     // Ww: 64 rows x 8 float4
            float4 w4 = *reinterpret_cast<const float4*>(Ww + (size_t)(d0 + dy) * KK + k0 + kq * 4);
            sAt[(kq * 4 + 0) * 66 + dy] = w4.x;
            sAt[(kq * 4 + 1) * 66 + dy] = w4.y;
            sAt[(kq * 4 + 2) * 66 + dy] = w4.z;
            sAt[(kq * 4 + 3) * 66 + dy] = w4.w;
            const int fq = tid & 15, ky = tid >> 4;    // Pw: 32 rows x 16 float4
            float4 p4 = *reinterpret_cast<const float4*>(Pw + (size_t)(k0 + ky) * FF + fq * 4);
            *reinterpret_cast<float4*>(sB + ky * 64 + fq * 4) = p4;
        }
        __syncthreads();

        const int tx = tid & 15, ty = tid >> 4;   // 16 f4-cols x 32 d-pairs
        float acc[2][4];
#pragma unroll
        for (int i = 0; i < 2; i++)
#pragma unroll
            for (int j = 0; j < 4; j++) acc[i][j] = 0.f;
#pragma unroll 8
        for (int k = 0; k < 32; k++) {
            float2 a2 = *reinterpret_cast<const float2*>(sAt + k * 66 + ty * 2);
            float4 b4 = *reinterpret_cast<const float4*>(sB + k * 64 + tx * 4);
            acc[0][0] += a2.x * b4.x; acc[0][1] += a2.x * b4.y; acc[0][2] += a2.x * b4.z; acc[0][3] += a2.x * b4.w;
            acc[1][0] += a2.y * b4.x; acc[1][1] += a2.y * b4.y; acc[1][2] += a2.y * b4.z; acc[1][3] += a2.y * b4.w;
        }
        // accumulate transposed: gMt[f][d]
        const int d = d0 + ty * 2;
#pragma unroll
        for (int j = 0; j < 4; j++) {
            const int f = tx * 4 + j;
            redadd(&gMt[(size_t)f * DD + d + 0], acc[0][j]);
            redadd(&gMt[(size_t)f * DD + d + 1], acc[1][j]);
        }
        __syncthreads();                       // GEMM done + sBig free for sY reuse
    } else {
        // block 128: c' = (W_b + b) - mean
        const float cv = Wb[tid] + bvec[tid];
        float s1 = cv;
#pragma unroll
        for (int o = 16; o > 0; o >>= 1) s1 += __shfl_down_sync(0xffffffffu, s1, o);
        if (lane == 0) sBig[wid] = s1;
        __syncthreads();
        if (wid == 0) {
            float t0 = (lane < 16) ? sBig[lane] : 0.f;
#pragma unroll
            for (int o = 8; o > 0; o >>= 1) t0 += __shfl_down_sync(0xffffffffu, t0, o);
            if (lane == 0) sBig[16] = t0;
        }
        __syncthreads();
        const float cbar = sBig[16] * (1.0f / DD);
        gCp[tid] = cv - cbar;
    }

    // ---------------- producer-done signal + wait ----------------
    if (tid == 0) {
        __threadfence();                       // reds + gCp visible
        unsigned int t = atomicAdd(&gProdDone, 1u);
        sEpoch = t / GRID;                     // epoch of this call
        if (bid < 64) {                        // consumers wait for all 129 producers
            const unsigned int target = (sEpoch + 1u) * GRID;
            volatile unsigned int* p = &gProdDone;
            while (*p < target) { }
            __threadfence();
        }
    }
    __syncthreads();

    // ---------------- Phase 3: blocks 0..63, one per batch ----------------
    if (bid < 64) {
        float* sY = sBig;
        // coalesced M row load: thread d reads gMt[f*512+d] (1 line / warp / instr)
        unsigned long long m2[32];
#pragma unroll
        for (int q = 0; q < 32; q++)
            m2[q] = pack2(gMt[(size_t)(2 * q) * DD + tid], gMt[(size_t)(2 * q + 1) * DD + tid]);
        const float cp = gCp[tid];
        float hacc = 0.f;

        for (int jc = 0; jc < n; jc += CH) {
            const int cnt = min(CH, n - jc);
            if (jc != 0) {
                __syncthreads();
                const int q = tid >> 4, f4 = tid & 15;
                if (q < cnt) {
                    const float4* xr = reinterpret_cast<const float4*>(xb + (size_t)(TT - 1 - (jc + q)) * FF);
                    *reinterpret_cast<float4*>(sXst + q * 64 + f4 * 4) = xr[f4];
                }
                __syncthreads();
            }

            // y for all cnt timesteps: pure FFMA2 stream, no syncs
#pragma unroll
            for (int tq = 0; tq < CH; tq++) {
                if (tq < cnt) {
                    unsigned long long acc2a = pack2(cp, 0.f);
                    unsigned long long acc2b = pack2(0.f, 0.f);
                    const ulonglong2* xs = reinterpret_cast<const ulonglong2*>(sXst + tq * 64);
#pragma unroll
                    for (int q = 0; q < 16; q++) {
                        ulonglong2 xv = xs[q];
                        fma2(acc2a, m2[2 * q + 0], xv.x);
                        fma2(acc2b, m2[2 * q + 1], xv.y);
                    }
                    float lo, hi, lo2, hi2;
                    unpack2(acc2a, lo, hi);
                    unpack2(acc2b, lo2, hi2);
                    sY[tq * NT + tid] = (lo + lo2) + (hi + hi2);
                } else {
                    sY[tq * NT + tid] = 0.f;
                }
            }
            __syncthreads();

            // one warp per timestep: (sum y, sum y^2) in a single level
            {
                const float* yr = sY + wid * NT;
                float s1 = 0.f, s2 = 0.f;
#pragma unroll
                for (int i = 0; i < 16; i++) {
                    float vv = yr[lane + 32 * i];
                    s1 += vv;
                    s2 += vv * vv;
                }
#pragma unroll
                for (int o = 16; o > 0; o >>= 1) {
                    s1 += __shfl_down_sync(0xffffffffu, s1, o);
                    s2 += __shfl_down_sync(0xffffffffu, s2, o);
                }
                if (lane == 0) {
                    const float mu = s1 * (1.0f / DD);
                    const float var = s2 * (1.0f / DD) - mu * mu;
                    float coef = 0.f;
                    if (wid < cnt)
                        coef = g * exp2f((float)(jc + wid) * l2omg) * rsqrtf(var + LN_EPS);
                    sMu[wid] = mu;
                    sCf[wid] = coef;
                }
            }
            __syncthreads();

#pragma unroll
            for (int t = 0; t < CH; t++) {
                if (t < cnt)
                    hacc += sCf[t] * (sY[t * NT + tid] - sMu[t]);
            }
        }

        const float Wsum = 1.0f - exp2f((float)TT * l2omg);
        out[(size_t)bid * DD + tid] = gamma[tid] * hacc + beta[tid] * Wsum;

        // signal: this block is done reading gMt
        __syncthreads();
        if (tid == 0) atomicAdd(&gReadDone, 1u);
    } else if (bid < 128) {
        // blocks 64..127: wait for all 64 readers, then re-zero gMt (off critical path)
        if (tid == 0) {
            const unsigned int target = (sEpoch + 1u) * 64u;
            volatile unsigned int* p = &gReadDone;
            while (*p < target) { }
            __threadfence();
        }
        __syncthreads();
        gMt[(size_t)(bid - 64) * NT + tid] = 0.f;
    }
}

// ---------------------------------------------------------------------------
// Inputs: x, theta1, phi1, theta2, phi2, w1, w2, b_g, P_w, W_w, W_b, b,
//         ln_gamma, ln_beta, alpha (alpha cancels inside LayerNorm).
// ---------------------------------------------------------------------------
extern "C" void kernel_launch(void* const* d_in, const int* in_sizes, int n_in,
                              void* d_out, int out_size) {
    const float* x     = (const float*)d_in[0];
    const float* th1   = (const float*)d_in[1];
    const float* ph1   = (const float*)d_in[2];
    const float* th2   = (const float*)d_in[3];
    const float* ph2   = (const float*)d_in[4];
    const float* w1p   = (const float*)d_in[5];
    const float* w2p   = (const float*)d_in[6];
    const float* bgp   = (const float*)d_in[7];
    const float* Pw    = (const float*)d_in[8];
    const float* Ww    = (const float*)d_in[9];
    const float* Wb    = (const float*)d_in[10];
    const float* bvec  = (const float*)d_in[11];
    const float* gamma = (const float*)d_in[12];
    const float* beta  = (const float*)d_in[13];

    mega<<<GRID, NT>>>(x, th1, ph1, th2, ph2, w1p, w2p, bgp,
                       Pw, Ww, Wb, bvec, gamma, beta, (float*)d_out);
}

// round 12
// speedup vs baseline: 1.2784x; 1.1193x over previous
#include <cuda_runtime.h>
#include <math.h>

#define BB 64
#define TT 2048
#define FF 64
#define KK 512
#define DD 512
#define LN_EPS 1e-5f
#define G_MIN 0.05f
#define G_MAX 0.95f
#define GRID 129
#define NT 512
#define CH 16          // timesteps per phase-3 chunk (n~12 -> single chunk)
#define ADSTR 132      // sAtDup row stride in floats (16B-aligned, bank-staggered)

// Scratch (__device__ globals; zero-initialized at load).
// Double-buffered M^T: epoch e uses buf e&1; blocks 64..127 zero buf (e+1)&1
// during call e (no tail wait). Launches are serialized, so this is safe.
__device__ __align__(16) float gMtBuf[2][FF * DD];      // [f][d], red.add targets
__device__ __align__(16) float gCp[DD];                 // c' = (W_b+b) - mean
__device__ unsigned int gProdDone;                      // +GRID per call (monotonic)

__device__ __forceinline__ unsigned long long pack2(float lo, float hi) {
    unsigned long long r;
    asm("mov.b64 %0, {%1, %2};" : "=l"(r) : "f"(lo), "f"(hi));
    return r;
}
__device__ __forceinline__ void unpack2(unsigned long long p, float& lo, float& hi) {
    asm("mov.b64 {%0, %1}, %2;" : "=f"(lo), "=f"(hi) : "l"(p));
}
// Packed dual-fp32 FMA (Blackwell f32x2 pipe)
__device__ __forceinline__ void fma2(unsigned long long& d, unsigned long long a, unsigned long long b) {
    asm("fma.rn.f32x2 %0, %1, %2, %0;" : "+l"(d) : "l"(a), "l"(b));
}
__device__ __forceinline__ void redadd(float* p, float v) {
    asm volatile("red.global.add.f32 [%0], %1;" :: "l"(p), "f"(v) : "memory");
}

__global__ void __launch_bounds__(NT, 1)
mega(const float* __restrict__ x,
     const float* __restrict__ th1, const float* __restrict__ ph1,
     const float* __restrict__ th2, const float* __restrict__ ph2,
     const float* __restrict__ w1p, const float* __restrict__ w2p,
     const float* __restrict__ bgp,
     const float* __restrict__ Pw,  const float* __restrict__ Ww,
     const float* __restrict__ Wb,  const float* __restrict__ bvec,
     const float* __restrict__ gamma, const float* __restrict__ beta,
     float* __restrict__ out) {
    __shared__ __align__(16) float sBig[CH * NT];    // 32KB: GEMM tiles OR sY
    __shared__ __align__(16) float sXst[CH * 64];    // staged x chunk (4KB)
    __shared__ float sMu[CH], sCf[CH];
    __shared__ unsigned int sEpoch;

    const int tid = threadIdx.x;
    const int bid = blockIdx.x;
    const int wid = tid >> 5, lane = tid & 31;

    // epoch: stable pre-increment value (all prior launches fully drained)
    if (tid == 0) sEpoch = (*(volatile unsigned int*)&gProdDone) / GRID;

    // ---------------- prologue: gate + chunk-0 x staging (blocks 0..63) ----------------
    float g = 0.f, l2omg = 0.f;
    int n = 0;
    const float* xb = x + (size_t)bid * TT * FF;
    if (bid < 64) {
        const float z1 = cosf(th1[0]) * cosf(ph1[0]);
        const float z2 = cosf(th2[0]) * cosf(ph2[0]);
        const float zg = w1p[0] * z1 + w2p[0] * z2 + bgp[0];
        g = 1.0f / (1.0f + expf(-zg));
        g = fminf(fmaxf(g, G_MIN), G_MAX);
        const float omg = 1.0f - g;
        l2omg = log2f(omg);
        n = (int)ceilf(-23.03f / logf(omg));
        if (n < 1) n = 1;
        if (n > TT) n = TT;

        const int cnt0 = min(CH, n);
        const int q = tid >> 4, f4 = tid & 15;
        if (q < cnt0) {
            const float4* xr = reinterpret_cast<const float4*>(xb + (size_t)(TT - 1 - q) * FF);
            *reinterpret_cast<float4*>(sXst + q * 64 + f4 * 4) = xr[f4];
        }
    }

    // ---------------- Phase 1: 128 GEMM blocks (f32x2, red.add) + block 128 (c') ----------------
    if (bid < 128) {
        float* sAtDup = sBig;                 // [k][d] dup pairs: 32 x (64 float2), stride ADSTR floats
        float* sB     = sBig + 32 * ADSTR;    // [k][f] 32x64
        const int ct = bid & 7;               // d tile
        const int ks = bid >> 3;              // k slice (16)
        const int d0 = ct * 64, k0 = ks * 32;

        {
            const int kq = tid & 7, dy = tid >> 3;     // Ww: 64 rows x 8 float4
            float4 w4 = *reinterpret_cast<const float4*>(Ww + (size_t)(d0 + dy) * KK + k0 + kq * 4);
            *reinterpret_cast<float2*>(sAtDup + (kq * 4 + 0) * ADSTR + dy * 2) = make_float2(w4.x, w4.x);
            *reinterpret_cast<float2*>(sAtDup + (kq * 4 + 1) * ADSTR + dy * 2) = make_float2(w4.y, w4.y);
            *reinterpret_cast<float2*>(sAtDup + (kq * 4 + 2) * ADSTR + dy * 2) = make_float2(w4.z, w4.z);
            *reinterpret_cast<float2*>(sAtDup + (kq * 4 + 3) * ADSTR + dy * 2) = make_float2(w4.w, w4.w);
            const int fq = tid & 15, ky = tid >> 4;    // Pw: 32 rows x 16 float4
            float4 p4 = *reinterpret_cast<const float4*>(Pw + (size_t)(k0 + ky) * FF + fq * 4);
            *reinterpret_cast<float4*>(sB + ky * 64 + fq * 4) = p4;
        }
        __syncthreads();

        // lane remap: 8 tx x 4 ty per warp -> 1 wf per operand per k
        const int tx = ((wid & 1) << 3) + (lane & 7);    // 0..15  (4 f each)
        const int ty = ((wid >> 1) << 2) + (lane >> 3);  // 0..31  (2 d each)

        unsigned long long acc2[2][2];
        acc2[0][0] = acc2[0][1] = acc2[1][0] = acc2[1][1] = pack2(0.f, 0.f);
#pragma unroll 8
        for (int k = 0; k < 32; k++) {
            ulonglong2 aD = *reinterpret_cast<const ulonglong2*>(sAtDup + k * ADSTR + ty * 4); // (a0,a0),(a1,a1)
            ulonglong2 bD = *reinterpret_cast<const ulonglong2*>(sB + k * 64 + tx * 4);        // (b0,b1),(b2,b3)
            fma2(acc2[0][0], aD.x, bD.x);
            fma2(acc2[0][1], aD.x, bD.y);
            fma2(acc2[1][0], aD.y, bD.x);
            fma2(acc2[1][1], aD.y, bD.y);
        }
        float* mbuf = gMtBuf[sEpoch & 1];
        const int d = d0 + ty * 2;
#pragma unroll
        for (int i = 0; i < 2; i++)
#pragma unroll
            for (int jp = 0; jp < 2; jp++) {
                float f0, f1;
                unpack2(acc2[i][jp], f0, f1);
                const int f = tx * 4 + jp * 2;
                redadd(&mbuf[(size_t)(f + 0) * DD + d + i], f0);
                redadd(&mbuf[(size_t)(f + 1) * DD + d + i], f1);
            }
        __syncthreads();                       // sBig free for sY reuse
    } else {
        // block 128: c' = (W_b + b) - mean
        const float cv = Wb[tid] + bvec[tid];
        float s1 = cv;
#pragma unroll
        for (int o = 16; o > 0; o >>= 1) s1 += __shfl_down_sync(0xffffffffu, s1, o);
        if (lane == 0) sBig[wid] = s1;
        __syncthreads();
        if (wid == 0) {
            float t0 = (lane < 16) ? sBig[lane] : 0.f;
#pragma unroll
            for (int o = 8; o > 0; o >>= 1) t0 += __shfl_down_sync(0xffffffffu, t0, o);
            if (lane == 0) sBig[16] = t0;
        }
        __syncthreads();
        const float cbar = sBig[16] * (1.0f / DD);
        gCp[tid] = cv - cbar;
    }

    // ---------------- producer-done signal + consumer wait ----------------
    if (tid == 0) {
        __threadfence();                       // reds + gCp visible
        atomicAdd(&gProdDone, 1u);
        if (bid < 64) {
            const unsigned int target = (sEpoch + 1u) * GRID;
            volatile unsigned int* p = &gProdDone;
            while (*p < target) { }
            __threadfence();
        }
    }
    __syncthreads();

    // ---------------- Phase 3: blocks 0..63 | zeroing: blocks 64..127 ----------------
    if (bid < 64) {
        const float* mbuf = gMtBuf[sEpoch & 1];
        float* sY = sBig;
        // coalesced M row load: thread d reads mbuf[f*512+d]
        unsigned long long m2[32];
#pragma unroll
        for (int q = 0; q < 32; q++)
            m2[q] = pack2(mbuf[(size_t)(2 * q) * DD + tid], mbuf[(size_t)(2 * q + 1) * DD + tid]);
        const float cp = gCp[tid];
        float hacc = 0.f;

        for (int jc = 0; jc < n; jc += CH) {
            const int cnt = min(CH, n - jc);
            if (jc != 0) {
                __syncthreads();
                const int q = tid >> 4, f4 = tid & 15;
                if (q < cnt) {
                    const float4* xr = reinterpret_cast<const float4*>(xb + (size_t)(TT - 1 - (jc + q)) * FF);
                    *reinterpret_cast<float4*>(sXst + q * 64 + f4 * 4) = xr[f4];
                }
                __syncthreads();
            }

            // y for all cnt timesteps: pure FFMA2 stream
#pragma unroll
            for (int tq = 0; tq < CH; tq++) {
                if (tq < cnt) {
                    unsigned long long acc2a = pack2(cp, 0.f);
                    unsigned long long acc2b = pack2(0.f, 0.f);
                    const ulonglong2* xs = reinterpret_cast<const ulonglong2*>(sXst + tq * 64);
#pragma unroll
                    for (int q = 0; q < 16; q++) {
                        ulonglong2 xv = xs[q];
                        fma2(acc2a, m2[2 * q + 0], xv.x);
                        fma2(acc2b, m2[2 * q + 1], xv.y);
                    }
                    float lo, hi, lo2, hi2;
                    unpack2(acc2a, lo, hi);
                    unpack2(acc2b, lo2, hi2);
                    sY[tq * NT + tid] = (lo + lo2) + (hi + hi2);
                } else {
                    sY[tq * NT + tid] = 0.f;
                }
            }
            __syncthreads();

            // one warp per timestep: (sum y, sum y^2)
            {
                const float* yr = sY + wid * NT;
                float s1 = 0.f, s2 = 0.f;
#pragma unroll
                for (int i = 0; i < 16; i++) {
                    float vv = yr[lane + 32 * i];
                    s1 += vv;
                    s2 += vv * vv;
                }
#pragma unroll
                for (int o = 16; o > 0; o >>= 1) {
                    s1 += __shfl_down_sync(0xffffffffu, s1, o);
                    s2 += __shfl_down_sync(0xffffffffu, s2, o);
                }
                if (lane == 0) {
                    const float mu = s1 * (1.0f / DD);
                    const float var = s2 * (1.0f / DD) - mu * mu;
                    float coef = 0.f;
                    if (wid < cnt)
                        coef = g * exp2f((float)(jc + wid) * l2omg) * rsqrtf(var + LN_EPS);
                    sMu[wid] = mu;
                    sCf[wid] = coef;
                }
            }
            __syncthreads();

#pragma unroll
            for (int t = 0; t < CH; t++) {
                if (t < cnt)
                    hacc += sCf[t] * (sY[t * NT + tid] - sMu[t]);
            }
        }

        const float Wsum = 1.0f - exp2f((float)TT * l2omg);
        out[(size_t)bid * DD + tid] = gamma[tid] * hacc + beta[tid] * Wsum;
    } else if (bid < 128) {
        // zero the OTHER buffer for the next call (no wait: disjoint from buf e&1)
        gMtBuf[(sEpoch + 1u) & 1][(size_t)(bid - 64) * NT + tid] = 0.f;
    }
}

// ---------------------------------------------------------------------------
// Inputs: x, theta1, phi1, theta2, phi2, w1, w2, b_g, P_w, W_w, W_b, b,
//         ln_gamma, ln_beta, alpha (alpha cancels inside LayerNorm).
// ---------------------------------------------------------------------------
extern "C" void kernel_launch(void* const* d_in, const int* in_sizes, int n_in,
                              void* d_out, int out_size) {
    const float* x     = (const float*)d_in[0];
    const float* th1   = (const float*)d_in[1];
    const float* ph1   = (const float*)d_in[2];
    const float* th2   = (const float*)d_in[3];
    const float* ph2   = (const float*)d_in[4];
    const float* w1p   = (const float*)d_in[5];
    const float* w2p   = (const float*)d_in[6];
    const float* bgp   = (const float*)d_in[7];
    const float* Pw    = (const float*)d_in[8];
    const float* Ww    = (const float*)d_in[9];
    const float* Wb    = (const float*)d_in[10];
    const float* bvec  = (const float*)d_in[11];
    const float* gamma = (const float*)d_in[12];
    const float* beta  = (const float*)d_in[13];

    mega<<<GRID, NT>>>(x, th1, ph1, th2, ph2, w1p, w2p, bgp,
                       Pw, Ww, Wb, bvec, gamma, beta, (float*)d_out);
}

// round 13
// speedup vs baseline: 1.2808x; 1.0019x over previous
#include <cuda_runtime.h>
#include <math.h>

#define BB 64
#define TT 2048
#define FF 64
#define KK 512
#define DD 512
#define LN_EPS 1e-5f
#define G_MIN 0.05f
#define G_MAX 0.95f
#define GRID 129
#define NT 512
#define CH 16          // timesteps per phase-3 chunk (n~12 -> single chunk)
#define ADSTR 132      // sAtDup row stride in floats (16B-aligned, bank-staggered)

// Scratch (__device__ globals; zero-initialized at load).
// Double-buffered interleaved M: buf[e&1], layout [f/2][d][2] (f-pairs innermost)
// so producer f32x2 accumulators red.v2 directly and consumers load u64 pairs.
// Blocks 64..127 zero buf (e+1)&1 during call e (no tail wait).
__device__ __align__(16) float gMtBuf[2][FF * DD];
__device__ __align__(16) float gCp[DD];                 // c' = (W_b+b) - mean
__device__ unsigned int gProdDone;                      // +GRID per call (monotonic)

__device__ __forceinline__ unsigned long long pack2(float lo, float hi) {
    unsigned long long r;
    asm("mov.b64 %0, {%1, %2};" : "=l"(r) : "f"(lo), "f"(hi));
    return r;
}
__device__ __forceinline__ void unpack2(unsigned long long p, float& lo, float& hi) {
    asm("mov.b64 {%0, %1}, %2;" : "=f"(lo), "=f"(hi) : "l"(p));
}
// Packed dual-fp32 FMA (Blackwell f32x2 pipe)
__device__ __forceinline__ void fma2(unsigned long long& d, unsigned long long a, unsigned long long b) {
    asm("fma.rn.f32x2 %0, %1, %2, %0;" : "+l"(d) : "l"(a), "l"(b));
}
__device__ __forceinline__ void redadd2(float* p, float v0, float v1) {
    asm volatile("red.global.v2.f32.add [%0], {%1, %2};" :: "l"(p), "f"(v0), "f"(v1) : "memory");
}
__device__ __forceinline__ void cpasync16(float* smem_dst, const float* gsrc) {
    unsigned int sa = (unsigned int)__cvta_generic_to_shared(smem_dst);
    asm volatile("cp.async.ca.shared.global [%0], [%1], 16;" :: "r"(sa), "l"(gsrc));
}

__global__ void __launch_bounds__(NT, 1)
mega(const float* __restrict__ x,
     const float* __restrict__ th1, const float* __restrict__ ph1,
     const float* __restrict__ th2, const float* __restrict__ ph2,
     const float* __restrict__ w1p, const float* __restrict__ w2p,
     const float* __restrict__ bgp,
     const float* __restrict__ Pw,  const float* __restrict__ Ww,
     const float* __restrict__ Wb,  const float* __restrict__ bvec,
     const float* __restrict__ gamma, const float* __restrict__ beta,
     float* __restrict__ out) {
    __shared__ __align__(16) float sBig[CH * NT];    // 32KB: GEMM tiles OR sY
    __shared__ __align__(16) float sXst[CH * 64];    // staged x chunk (4KB)
    __shared__ float sMu[CH], sCf[CH];
    __shared__ unsigned int sEpoch;

    const int tid = threadIdx.x;
    const int bid = blockIdx.x;
    const int wid = tid >> 5, lane = tid & 31;

    // epoch: stable pre-increment value (all prior launches fully drained)
    if (tid == 0) sEpoch = (*(volatile unsigned int*)&gProdDone) / GRID;

    // ---------------- prologue: async chunk-0 x staging (blocks 0..63) ----------------
    const float* xb = x + (size_t)bid * TT * FF;
    if (bid < 64) {
        // stage CH rows unconditionally via cp.async (non-blocking; waited after spin)
        const int q = tid >> 4, f4 = tid & 15;
        if (q < CH)
            cpasync16(sXst + q * 64 + f4 * 4, xb + (size_t)(TT - 1 - q) * FF + f4 * 4);
        asm volatile("cp.async.commit_group;" ::: "memory");
    }

    // ---------------- Phase 1: 128 GEMM blocks (f32x2, red.v2) + block 128 (c') ----------------
    if (bid < 128) {
        float* sAtDup = sBig;                 // [k][d] dup pairs: 32 x (64 float2), stride ADSTR
        float* sB     = sBig + 32 * ADSTR;    // [k][f] 32x64
        const int ct = bid & 7;               // d tile
        const int ks = bid >> 3;              // k slice (16)
        const int d0 = ct * 64, k0 = ks * 32;

        {
            const int kq = tid & 7, dy = tid >> 3;     // Ww: 64 rows x 8 float4
            float4 w4 = *reinterpret_cast<const float4*>(Ww + (size_t)(d0 + dy) * KK + k0 + kq * 4);
            *reinterpret_cast<float2*>(sAtDup + (kq * 4 + 0) * ADSTR + dy * 2) = make_float2(w4.x, w4.x);
            *reinterpret_cast<float2*>(sAtDup + (kq * 4 + 1) * ADSTR + dy * 2) = make_float2(w4.y, w4.y);
            *reinterpret_cast<float2*>(sAtDup + (kq * 4 + 2) * ADSTR + dy * 2) = make_float2(w4.z, w4.z);
            *reinterpret_cast<float2*>(sAtDup + (kq * 4 + 3) * ADSTR + dy * 2) = make_float2(w4.w, w4.w);
            const int fq = tid & 15, ky = tid >> 4;    // Pw: 32 rows x 16 float4
            float4 p4 = *reinterpret_cast<const float4*>(Pw + (size_t)(k0 + ky) * FF + fq * 4);
            *reinterpret_cast<float4*>(sB + ky * 64 + fq * 4) = p4;
        }
        __syncthreads();

        // lane remap: 8 tx x 4 ty per warp
        const int tx = ((wid & 1) << 3) + (lane & 7);    // 0..15  (4 f each)
        const int ty = ((wid >> 1) << 2) + (lane >> 3);  // 0..31  (2 d each)

        unsigned long long acc2[2][2];
        acc2[0][0] = acc2[0][1] = acc2[1][0] = acc2[1][1] = pack2(0.f, 0.f);
#pragma unroll 8
        for (int k = 0; k < 32; k++) {
            ulonglong2 aD = *reinterpret_cast<const ulonglong2*>(sAtDup + k * ADSTR + ty * 4); // (a0,a0),(a1,a1)
            ulonglong2 bD = *reinterpret_cast<const ulonglong2*>(sB + k * 64 + tx * 4);        // (b0,b1),(b2,b3)
            fma2(acc2[0][0], aD.x, bD.x);
            fma2(acc2[0][1], aD.x, bD.y);
            fma2(acc2[1][0], aD.y, bD.x);
            fma2(acc2[1][1], aD.y, bD.y);
        }
        // interleaved target: gMtI[(f>>1)*1024 + d*2 + (f&1)]; acc2[i][jp] = (f, f+1) vals
        float* mbuf = gMtBuf[sEpoch & 1];
        const int d = d0 + ty * 2;
#pragma unroll
        for (int i = 0; i < 2; i++)
#pragma unroll
            for (int jp = 0; jp < 2; jp++) {
                float f0, f1;
                unpack2(acc2[i][jp], f0, f1);
                const int fh = tx * 2 + jp;            // f-pair index (f = 2*fh)
                redadd2(&mbuf[(size_t)fh * 1024 + (d + i) * 2], f0, f1);
            }
        __syncthreads();                       // sBig free for sY reuse
    } else {
        // block 128: c' = (W_b + b) - mean
        const float cv = Wb[tid] + bvec[tid];
        float s1 = cv;
#pragma unroll
        for (int o = 16; o > 0; o >>= 1) s1 += __shfl_down_sync(0xffffffffu, s1, o);
        if (lane == 0) sBig[wid] = s1;
        __syncthreads();
        if (wid == 0) {
            float t0 = (lane < 16) ? sBig[lane] : 0.f;
#pragma unroll
            for (int o = 8; o > 0; o >>= 1) t0 += __shfl_down_sync(0xffffffffu, t0, o);
            if (lane == 0) sBig[16] = t0;
        }
        __syncthreads();
        const float cbar = sBig[16] * (1.0f / DD);
        gCp[tid] = cv - cbar;
    }

    // ---------------- producer-done (release) + consumer wait ----------------
    if (tid == 0) {
        asm volatile("red.release.gpu.global.add.u32 [%0], %1;"
                     :: "l"(&gProdDone), "r"(1u) : "memory");
        if (bid < 64) {
            const unsigned int target = (sEpoch + 1u) * GRID;
            volatile unsigned int* p = &gProdDone;
            while (*p < target) { }
            __threadfence();
        }
    }

    // gate math (blocks 0..63): overlaps the spin of thread 0 / barrier
    float g = 0.f, l2omg = 0.f;
    int n = 0;
    if (bid < 64) {
        const float z1 = cosf(th1[0]) * cosf(ph1[0]);
        const float z2 = cosf(th2[0]) * cosf(ph2[0]);
        const float zg = w1p[0] * z1 + w2p[0] * z2 + bgp[0];
        g = 1.0f / (1.0f + expf(-zg));
        g = fminf(fmaxf(g, G_MIN), G_MAX);
        const float omg = 1.0f - g;
        l2omg = log2f(omg);
        n = (int)ceilf(-23.03f / logf(omg));
        if (n < 1) n = 1;
        if (n > TT) n = TT;
    }
    __syncthreads();

    // ---------------- Phase 3: blocks 0..63 | zeroing: blocks 64..127 ----------------
    if (bid < 64) {
        const float* mbuf = gMtBuf[sEpoch & 1];
        float* sY = sBig;
        // m2[q] = (M[2q][d], M[2q+1][d]) : one coalesced u64 load each
        unsigned long long m2[32];
#pragma unroll
        for (int q = 0; q < 32; q++)
            m2[q] = *reinterpret_cast<const unsigned long long*>(mbuf + (size_t)q * 1024 + tid * 2);
        const float cp = gCp[tid];
        asm volatile("cp.async.wait_group 0;" ::: "memory");
        __syncthreads();
        float hacc = 0.f;

        for (int jc = 0; jc < n; jc += CH) {
            const int cnt = min(CH, n - jc);
            if (jc != 0) {
                __syncthreads();
                const int q = tid >> 4, f4 = tid & 15;
                if (q < cnt) {
                    const float4* xr = reinterpret_cast<const float4*>(xb + (size_t)(TT - 1 - (jc + q)) * FF);
                    *reinterpret_cast<float4*>(sXst + q * 64 + f4 * 4) = xr[f4];
                }
                __syncthreads();
            }

            // y for all cnt timesteps: pure FFMA2 stream
#pragma unroll
            for (int tq = 0; tq < CH; tq++) {
                if (tq < cnt) {
                    unsigned long long acc2a = pack2(cp, 0.f);
                    unsigned long long acc2b = pack2(0.f, 0.f);
                    const ulonglong2* xs = reinterpret_cast<const ulonglong2*>(sXst + tq * 64);
#pragma unroll
                    for (int q = 0; q < 16; q++) {
                        ulonglong2 xv = xs[q];
                        fma2(acc2a, m2[2 * q + 0], xv.x);
                        fma2(acc2b, m2[2 * q + 1], xv.y);
                    }
                    float lo, hi, lo2, hi2;
                    unpack2(acc2a, lo, hi);
                    unpack2(acc2b, lo2, hi2);
                    sY[tq * NT + tid] = (lo + lo2) + (hi + hi2);
                } else {
                    sY[tq * NT + tid] = 0.f;
                }
            }
            __syncthreads();

            // one warp per timestep: (sum y, sum y^2)
            {
                const float* yr = sY + wid * NT;
                float s1 = 0.f, s2 = 0.f;
#pragma unroll
                for (int i = 0; i < 16; i++) {
                    float vv = yr[lane + 32 * i];
                    s1 += vv;
                    s2 += vv * vv;
                }
#pragma unroll
                for (int o = 16; o > 0; o >>= 1) {
                    s1 += __shfl_down_sync(0xffffffffu, s1, o);
                    s2 += __shfl_down_sync(0xffffffffu, s2, o);
                }
                if (lane == 0) {
                    const float mu = s1 * (1.0f / DD);
                    const float var = s2 * (1.0f / DD) - mu * mu;
                    float coef = 0.f;
                    if (wid < cnt)
                        coef = g * exp2f((float)(jc + wid) * l2omg) * rsqrtf(var + LN_EPS);
                    sMu[wid] = mu;
                    sCf[wid] = coef;
                }
            }
            __syncthreads();

#pragma unroll
            for (int t = 0; t < CH; t++) {
                if (t < cnt)
                    hacc += sCf[t] * (sY[t * NT + tid] - sMu[t]);
            }
        }

        const float Wsum = 1.0f - exp2f((float)TT * l2omg);
        out[(size_t)bid * DD + tid] = gamma[tid] * hacc + beta[tid] * Wsum;
    } else if (bid < 128) {
        // zero the OTHER buffer for the next call (disjoint from buf e&1)
        gMtBuf[(sEpoch + 1u) & 1][(size_t)(bid - 64) * NT + tid] = 0.f;
    }
}

// ---------------------------------------------------------------------------
// Inputs: x, theta1, phi1, theta2, phi2, w1, w2, b_g, P_w, W_w, W_b, b,
//         ln_gamma, ln_beta, alpha (alpha cancels inside LayerNorm).
// ---------------------------------------------------------------------------
extern "C" void kernel_launch(void* const* d_in, const int* in_sizes, int n_in,
                              void* d_out, int out_size) {
    const float* x     = (const float*)d_in[0];
    const float* th1   = (const float*)d_in[1];
    const float* ph1   = (const float*)d_in[2];
    const float* th2   = (const float*)d_in[3];
    const float* ph2   = (const float*)d_in[4];
    const float* w1p   = (const float*)d_in[5];
    const float* w2p   = (const float*)d_in[6];
    const float* bgp   = (const float*)d_in[7];
    const float* Pw    = (const float*)d_in[8];
    const float* Ww    = (const float*)d_in[9];
    const float* Wb    = (const float*)d_in[10];
    const float* bvec  = (const float*)d_in[11];
    const float* gamma = (const float*)d_in[12];
    const float* beta  = (const float*)d_in[13];

    mega<<<GRID, NT>>>(x, th1, ph1, th2, ph2, w1p, w2p, bgp,
                       Pw, Ww, Wb, bvec, gamma, beta, (float*)d_out);
}